// round 14
// baseline (speedup 1.0000x reference)
#include <cuda_runtime.h>
#include <cuda_fp16.h>
#include <cstdint>
#include <math.h>

// Problem constants
#define NB   4
#define NH   66
#define NW   66
#define NC   32
#define NF   64
#define HO   64
#define WO   64

// GEMM: per channel K = 176 (9 cij * 18 slots = 162 used, pad to 11 k16-steps)
#define KC        176
#define KI        11                  // k16 steps
#define PXB       64                  // pixels per block (one output row)
#define A_BYTES   (PXB * KC * 2)      // 22528 (fragment-major)
#define B_BYTES   (64 * KC * 2)       // 22528 (fragment-major)
#define NOUT      (NB * HO * WO * NF) // 1048576

// smem offsets: two A fragment buffers only (B comes via LDG from L2)
#define SM_A0     0
#define SM_A1     22528
#define SM_TOTAL  45056

// fused prep kernel grid partition
#define PREP_BF_BLOCKS   352          // 90112 threads * 4 halves = 360448 B halves
#define PREP_FEAT_BLOCKS 2178         // 557568 feature elements
#define PREP_INIT_BLOCKS 1024         // 262144 float4 out-init
#define PREP_BLOCKS (PREP_BF_BLOCKS + PREP_FEAT_BLOCKS + PREP_INIT_BLOCKS)

// ---------------------------------------------------------------------------
// Device globals (no allocation allowed)
// B fragment images: [c][ki][ni][lane][4 halves]  (32 * 22528 B = 704 KB, L2-resident)
__device__ __align__(16) __half g_Bfrag[32 * (B_BYTES / 2)];
__device__ __align__(16) float4 g_featP[NC * NB * NH * NW];  // [c][b][h][w]: (t, silu, g-bits, 0)

// ---------------------------------------------------------------------------
__device__ __forceinline__ uint32_t smem_u32(const void* p) {
    uint32_t a;
    asm("{ .reg .u64 t; cvta.to.shared.u64 t, %1; cvt.u32.u64 %0, t; }" : "=r"(a) : "l"(p));
    return a;
}
__device__ __forceinline__ void mma16816(float* d, const uint32_t* a, const uint32_t* b) {
    asm volatile("mma.sync.aligned.m16n8k16.row.col.f32.f16.f16.f32 "
                 "{%0,%1,%2,%3}, {%4,%5,%6,%7}, {%8,%9}, {%0,%1,%2,%3};"
                 : "+f"(d[0]), "+f"(d[1]), "+f"(d[2]), "+f"(d[3])
                 : "r"(a[0]), "r"(a[1]), "r"(a[2]), "r"(a[3]), "r"(b[0]), "r"(b[1]));
}

// A fragment-major byte address for logical element (pixel r, col)
__device__ __forceinline__ uint32_t a_off(uint32_t base_t, int col) {
    int ki = col >> 4, kk = col & 15;
    return base_t + ki * 512 + (((kk >> 1) & 3) << 4) + ((kk & 1) << 1) + ((kk >> 3) << 3);
}

// ---------------------------------------------------------------------------
// Fused prep kernel: [0,352) B-fragments, [352,2530) features, [2530,3554) out=bias
__global__ void prep_kernel(const float* __restrict__ x,
                            const float* __restrict__ cp,
                            const float* __restrict__ w_spline,
                            const float* __restrict__ w_silu,
                            const float* __restrict__ bias,
                            float* __restrict__ out)
{
    int bid = blockIdx.x;
    int tid = threadIdx.x;

    if (bid < PREP_BF_BLOCKS) {
        // ---- B fragment images: 4 halves (one uint2) per thread ----
        int t    = bid * 256 + tid;                 // [0, 90112)
        int lane = t & 31;
        int ni   = (t >> 5) & 7;
        int rest = t >> 8;
        int ki   = rest % KI;
        int c    = rest / KI;
        int gid  = lane >> 2, tig = lane & 3;
        int f    = ni * 8 + gid;
        int kbase = ki * 16 + 2 * tig;
        __half h[4];
#pragma unroll
        for (int bb = 0; bb < 4; bb++) {
            int k = kbase + (bb & 1) + ((bb >> 1) << 3);
            float v = 0.0f;
            if (k < 162) {
                int q = k / 18;
                int s = k - 18 * q;
                int iw = (f * 32 + c) * 9 + q;
                v = (s < 17) ? w_spline[iw] * cp[iw * 17 + s] : w_silu[iw];
            }
            h[bb] = __float2half_rn(v);
        }
        *(uint2*)(g_Bfrag + (size_t)t * 4) = *(const uint2*)h;
    } else if (bid < PREP_BF_BLOCKS + PREP_FEAT_BLOCKS) {
        // ---- planar features ----
        int i = (bid - PREP_BF_BLOCKS) * 256 + tid;  // [0, 557568)
        int c   = i & 31;
        int pos = i >> 5;
        float v  = x[i];
        float s  = v / (1.0f + __expf(-v));
        float xc = fminf(1.0f, fmaxf(-1.0f, v));
        float u  = (xc + 1.0f) * 8.0f;
        int   g  = (int)u;
        g = (g > 15) ? 15 : g;
        float t  = u - (float)g;
        g_featP[(size_t)c * (NB * NH * NW) + pos] = make_float4(t, s, __int_as_float(g), 0.0f);
    } else {
        // ---- out = bias (main kernel RED.ADDs partials on top) ----
        int j = (bid - PREP_BF_BLOCKS - PREP_FEAT_BLOCKS) * 256 + tid;  // [0, 262144)
        ((float4*)out)[j] = __ldg(((const float4*)bias) + (j & 15));
    }
}

// ---------------------------------------------------------------------------
// Main HMMA kernel: 512 blocks x 256 threads, 3 blocks/SM (45KB smem, <=85 regs).
// Block = (split s, b, 1 output row) = 64 px, 16 channels [s*16, s*16+16).
// Warp (wm = wid>>1, wn = wid&1): M rows (pixels) [16*wm, +16), N cols [32*wn, +32).
// Per channel: sync -> prefetch feat(cc+1) regs -> MMA(cc) [A LDS, B LDG dist-2 ring]
//              -> scatter(cc+1). Epilogue: RED.ADD into bias-initialized out.
__global__ void __launch_bounds__(256, 3)
kan_hmma_kernel(float* __restrict__ out)
{
    extern __shared__ char smem[];
    const uint32_t sbase = smem_u32(smem);
    const int tid  = threadIdx.x;
    const int wid  = tid >> 5;
    const int lane = tid & 31;
    const int blk  = blockIdx.x;
    const int s    = blk >> 8;            // channel split (0,1)
    const int b    = (blk >> 6) & 3;
    const int h0   = blk & 63;
    const int c0   = s * 16;

    // zero both A fragment buffers (cols never written stay 0 forever)
    {
        float4* az = (float4*)smem;
#pragma unroll
        for (int i = 0; i < 11; i++) {
            int j = tid + i * 256;
            if (j < (2 * A_BYTES) / 16) az[j] = make_float4(0.f, 0.f, 0.f, 0.f);
        }
    }
    __syncthreads();   // A zeroing visible before scatter

    // scatter config: 4 quarters of threads handle cij groups {0,1,2},{3,4},{5,6},{7,8}
    const int px      = tid & 63;
    const int quarter = tid >> 6;
    const int qbase   = (quarter == 0) ? 0 : (quarter * 2 + 1);
    const int qcnt    = (quarter == 0) ? 3 : 2;
    const int mi      = px >> 4, row16 = px & 15;
    const uint32_t base_t0 = (uint32_t)(mi * 5632 + ((row16 & 7) << 6) + (((row16 >> 3) & 1) << 2));

    const int wm = wid >> 1, wn = wid & 1;

    float acc[4][4];
#pragma unroll
    for (int nt = 0; nt < 4; nt++)
#pragma unroll
        for (int e = 0; e < 4; e++) acc[nt][e] = 0.0f;

    uint32_t gpack[2] = {0u, 0u};

    // feat loads for channel cc (<=3 per thread)
    auto loadFeat = [&](int cc, float4* fv) {
        int ca = c0 + cc;
#pragma unroll
        for (int qi = 0; qi < 3; qi++) {
            if (qi >= qcnt) break;
            int q  = qbase + qi;
            int ii = q / 3, jj = q - 3 * ii;
            fv[qi] = __ldg(g_featP + ((size_t)(ca * NB + b) * NH + (h0 + ii)) * NW + (px + jj));
        }
    };
    // scatter channel cc from prefetched regs into buffer cc&1 (zero stale from cc-2)
    auto scatter = [&](int cc, const float4* fv) {
        char* Ab = smem + ((cc & 1) ? SM_A1 : SM_A0);
#pragma unroll
        for (int qi = 0; qi < 3; qi++) {
            if (qi >= qcnt) break;
            int q = qbase + qi;
            int g = __float_as_int(fv[qi].z);
            if (cc >= 2) {
                int gold = (gpack[cc & 1] >> (4 * qi)) & 15;
                int oc   = q * 18 + gold;
                *(__half*)(Ab + a_off(base_t0, oc))     = __ushort_as_half((unsigned short)0);
                *(__half*)(Ab + a_off(base_t0, oc + 1)) = __ushort_as_half((unsigned short)0);
            }
            int col0 = q * 18 + g;
            *(__half*)(Ab + a_off(base_t0, col0))        = __float2half_rn(1.0f - fv[qi].x);
            *(__half*)(Ab + a_off(base_t0, col0 + 1))    = __float2half_rn(fv[qi].x);
            *(__half*)(Ab + a_off(base_t0, q * 18 + 17)) = __float2half_rn(fv[qi].y);
            gpack[cc & 1] = (gpack[cc & 1] & ~(15u << (4 * qi))) | ((uint32_t)g << (4 * qi));
        }
    };

    {
        float4 fv[3];
        loadFeat(0, fv);
        scatter(0, fv);
    }

    for (int cc = 0; cc < 16; cc++) {
        const int buf = cc & 1;
        // barrier: scatter(cc) visible; MMA(cc-1) LDS of same-parity buffer retired
        __syncthreads();

        // prefetch feats for cc+1 into registers (hidden under MMA below)
        float4 fv[3];
        if (cc < 15) loadFeat(cc + 1, fv);

        // ---- MMA(cc): A frags via LDS, B frags via LDG with dist-2 register ring ----
        {
            const uint32_t abase = sbase + (buf ? SM_A1 : SM_A0) + (uint32_t)(wm * 5632 + lane * 16);
            const __half*  Bc    = g_Bfrag + (size_t)(c0 + cc) * (B_BYTES / 2) + lane * 4
                                          + (size_t)wn * 4 * 128;
            // preload ki=0,1 B fragments (4 ni each)
            uint2 bq[2][4];
#pragma unroll
            for (int p = 0; p < 2; p++)
#pragma unroll
                for (int nt = 0; nt < 4; nt++)
                    bq[p][nt] = __ldg((const uint2*)(Bc + (size_t)(p * 8 + nt) * 128));
#pragma unroll
            for (int ki = 0; ki < KI; ki++) {
                const int p = ki & 1;
                // issue loads for ki+2 first (land after this ki + next ki of MMAs)
                uint2 tnew[4];
                if (ki < KI - 2) {
#pragma unroll
                    for (int nt = 0; nt < 4; nt++)
                        tnew[nt] = __ldg((const uint2*)(Bc + (size_t)((ki + 2) * 8 + nt) * 128));
                }
                uint32_t afr[4];
                asm volatile("ld.shared.v4.b32 {%0,%1,%2,%3}, [%4];"
                             : "=r"(afr[0]), "=r"(afr[1]), "=r"(afr[2]), "=r"(afr[3])
                             : "r"(abase + (uint32_t)(ki * 512)));
#pragma unroll
                for (int nt = 0; nt < 4; nt++)
                    mma16816(acc[nt], afr, (const uint32_t*)&bq[p][nt]);
                if (ki < KI - 2) {
#pragma unroll
                    for (int nt = 0; nt < 4; nt++) bq[p][nt] = tnew[nt];
                }
            }
        }

        // ---- scatter(cc+1) into the opposite A buffer (overlaps tensor-pipe drain) ----
        if (cc < 15) scatter(cc + 1, fv);
    }

    // ---- epilogue: RED.ADD partial accumulators into bias-initialized out ----
    {
        const int gid = lane >> 2, tig = lane & 3;
#pragma unroll
        for (int nt = 0; nt < 4; nt++) {
            int f  = wn * 32 + nt * 8 + 2 * tig;
            int r0 = wm * 16 + gid;
            float* o0 = out + (((size_t)(b * HO) + h0) * WO + r0) * NF + f;
            float* o1 = out + (((size_t)(b * HO) + h0) * WO + (r0 + 8)) * NF + f;
            atomicAdd(o0,     acc[nt][0]);
            atomicAdd(o0 + 1, acc[nt][1]);
            atomicAdd(o1,     acc[nt][2]);
            atomicAdd(o1 + 1, acc[nt][3]);
        }
    }
}

// ---------------------------------------------------------------------------
extern "C" void kernel_launch(void* const* d_in, const int* in_sizes, int n_in,
                              void* d_out, int out_size)
{
    const float* x    = (const float*)d_in[0];   // (4,66,66,32)
    const float* cp   = (const float*)d_in[1];   // (64,32,3,3,17)
    const float* wsp  = (const float*)d_in[2];   // (64,32,3,3)
    const float* wsi  = (const float*)d_in[3];   // (64,32,3,3)
    const float* bias = (const float*)d_in[4];   // (64,)
    float* out        = (float*)d_out;           // (4,64,64,64)

    cudaFuncSetAttribute(kan_hmma_kernel, cudaFuncAttributeMaxDynamicSharedMemorySize, SM_TOTAL);

    prep_kernel<<<PREP_BLOCKS, 256>>>(x, cp, wsp, wsi, bias, out);
    kan_hmma_kernel<<<512, 256, SM_TOTAL>>>(out);
}

// round 15
// speedup vs baseline: 2.1951x; 2.1951x over previous
#include <cuda_runtime.h>
#include <cuda_fp16.h>
#include <cstdint>
#include <math.h>

// Problem constants
#define NB   4
#define NH   66
#define NW   66
#define NC   32
#define NF   64
#define HO   64
#define WO   64

// GEMM: per channel K = 176 (9 cij * 18 slots = 162 used, pad to 11 k16-steps)
#define KC        176
#define KI        11                  // k16 steps
#define A_BYTES   (128 * KC * 2)      // 45056 (fragment-major)
#define B_BYTES   (64 * KC * 2)       // 22528 (fragment-major)
#define NOUT      (NB * HO * WO * NF) // 1048576

// smem: two A fragment buffers (B via LDG from L2/L1); epilogue reduction reuses A0
#define SM_A0     0
#define SM_A1     45056
#define SM_TOTAL  90112

// fused prep kernel grid partition
#define PREP_BF_BLOCKS   352          // 90112 threads * 4 halves = 360448 B halves
#define PREP_FEAT_BLOCKS 2178         // 557568 feature elements
#define PREP_INIT_BLOCKS 1024         // 262144 float4 out-init
#define PREP_BLOCKS (PREP_BF_BLOCKS + PREP_FEAT_BLOCKS + PREP_INIT_BLOCKS)

// ---------------------------------------------------------------------------
// Device globals (no allocation allowed)
// B fragment images: [c][ki][ni][lane][4 halves]  (32 * 22528 B = 704 KB, L2-resident)
__device__ __align__(16) __half g_Bfrag[32 * (B_BYTES / 2)];
__device__ __align__(16) float4 g_featP[NC * NB * NH * NW];  // [c][b][h][w]: (t, silu, g-bits, 0)

// ---------------------------------------------------------------------------
__device__ __forceinline__ uint32_t smem_u32(const void* p) {
    uint32_t a;
    asm("{ .reg .u64 t; cvta.to.shared.u64 t, %1; cvt.u32.u64 %0, t; }" : "=r"(a) : "l"(p));
    return a;
}
__device__ __forceinline__ void mma16816(float* d, const uint32_t* a, const uint32_t* b) {
    asm volatile("mma.sync.aligned.m16n8k16.row.col.f32.f16.f16.f32 "
                 "{%0,%1,%2,%3}, {%4,%5,%6,%7}, {%8,%9}, {%0,%1,%2,%3};"
                 : "+f"(d[0]), "+f"(d[1]), "+f"(d[2]), "+f"(d[3])
                 : "r"(a[0]), "r"(a[1]), "r"(a[2]), "r"(a[3]), "r"(b[0]), "r"(b[1]));
}

// A fragment-major byte address for logical element (pixel r, col)
__device__ __forceinline__ uint32_t a_off(uint32_t base_t, int col) {
    int ki = col >> 4, kk = col & 15;
    return base_t + ki * 512 + (((kk >> 1) & 3) << 4) + ((kk & 1) << 1) + ((kk >> 3) << 3);
}

// ---------------------------------------------------------------------------
// Fused prep kernel: [0,352) B-fragments, [352,2530) features, [2530,3554) out=bias
__global__ void prep_kernel(const float* __restrict__ x,
                            const float* __restrict__ cp,
                            const float* __restrict__ w_spline,
                            const float* __restrict__ w_silu,
                            const float* __restrict__ bias,
                            float* __restrict__ out)
{
    int bid = blockIdx.x;
    int tid = threadIdx.x;

    if (bid < PREP_BF_BLOCKS) {
        int t    = bid * 256 + tid;                 // [0, 90112)
        int lane = t & 31;
        int ni   = (t >> 5) & 7;
        int rest = t >> 8;
        int ki   = rest % KI;
        int c    = rest / KI;
        int gid  = lane >> 2, tig = lane & 3;
        int f    = ni * 8 + gid;
        int kbase = ki * 16 + 2 * tig;
        __half h[4];
#pragma unroll
        for (int bb = 0; bb < 4; bb++) {
            int k = kbase + (bb & 1) + ((bb >> 1) << 3);
            float v = 0.0f;
            if (k < 162) {
                int q = k / 18;
                int s = k - 18 * q;
                int iw = (f * 32 + c) * 9 + q;
                v = (s < 17) ? w_spline[iw] * cp[iw * 17 + s] : w_silu[iw];
            }
            h[bb] = __float2half_rn(v);
        }
        *(uint2*)(g_Bfrag + (size_t)t * 4) = *(const uint2*)h;
    } else if (bid < PREP_BF_BLOCKS + PREP_FEAT_BLOCKS) {
        int i = (bid - PREP_BF_BLOCKS) * 256 + tid;  // [0, 557568)
        int c   = i & 31;
        int pos = i >> 5;
        float v  = x[i];
        float s  = v / (1.0f + __expf(-v));
        float xc = fminf(1.0f, fmaxf(-1.0f, v));
        float u  = (xc + 1.0f) * 8.0f;
        int   g  = (int)u;
        g = (g > 15) ? 15 : g;
        float t  = u - (float)g;
        g_featP[(size_t)c * (NB * NH * NW) + pos] = make_float4(t, s, __int_as_float(g), 0.0f);
    } else {
        int j = (bid - PREP_BF_BLOCKS - PREP_FEAT_BLOCKS) * 256 + tid;  // [0, 262144)
        ((float4*)out)[j] = __ldg(((const float4*)bias) + (j & 15));
    }
}

// ---------------------------------------------------------------------------
// Main HMMA kernel: 256 blocks x 256 threads, 2 blocks/SM (90KB smem, <=128 regs).
// Block = (split s, b, 2 output rows) = 128 px, 16 channels [s*16, +16).
// Warp (wm = wid&3, kh = wid>>2): M rows [32*wm, +32), ALL 64 f, K-half kh.
//   -> each A fragment byte is read by exactly ONE warp (was 2); B by 4 (unchanged).
// Epilogue: kh=1 partials reduced into kh=0 accs via SMEM, then RED.ADD into out.
__global__ void __launch_bounds__(256, 2)
kan_hmma_kernel(float* __restrict__ out)
{
    extern __shared__ char smem[];
    const uint32_t sbase = smem_u32(smem);
    const int tid  = threadIdx.x;
    const int wid  = tid >> 5;
    const int lane = tid & 31;
    const int blk  = blockIdx.x;
    const int s    = blk >> 7;            // channel split (0,1)
    const int b    = (blk >> 5) & 3;
    const int h0   = (blk & 31) * 2;
    const int c0   = s * 16;

    // zero both A fragment buffers (cols never written stay 0 forever)
    {
        float4* az = (float4*)smem;
#pragma unroll 4
        for (int i = tid; i < (2 * A_BYTES) / 16; i += 256) az[i] = make_float4(0.f, 0.f, 0.f, 0.f);
    }
    __syncthreads();   // A zeroing visible before scatter

    // scatter config: threads 0-127 -> pixel r, q 0..3; 128-255 -> same r, q 4..8
    const int r     = tid & 127;
    const int qbase = (tid >> 7) ? 4 : 0;
    const int qcnt  = (tid >> 7) ? 5 : 4;
    const int rh    = r >> 6, rw = r & 63;
    const int mi    = r >> 4, row16 = r & 15;
    const uint32_t base_t0 = (uint32_t)(mi * 5632 + ((row16 & 7) << 6) + (((row16 >> 3) & 1) << 2));

    const int wm = wid & 3;               // M group (32 px)
    const int kh = wid >> 2;              // K half: 0 -> ki 0..5, 1 -> ki 6..10

    float acc[2][8][4];
#pragma unroll
    for (int mt = 0; mt < 2; mt++)
#pragma unroll
        for (int nt = 0; nt < 8; nt++)
#pragma unroll
            for (int e = 0; e < 4; e++) acc[mt][nt][e] = 0.0f;

    uint32_t gpack[2] = {0u, 0u};

    // build A(cc) into buffer cc&1 (zero stale slots from cc-2 first)
    auto build = [&](int cc) {
        char* Ab = smem + ((cc & 1) ? SM_A1 : SM_A0);
        int ca = c0 + cc;
#pragma unroll
        for (int qi = 0; qi < 5; qi++) {
            if (qi >= qcnt) break;
            int q  = qbase + qi;
            int ii = q / 3, jj = q - 3 * ii;
            float4 fv = __ldg(g_featP + ((size_t)(ca * NB + b) * NH + (h0 + rh + ii)) * NW + (rw + jj));
            int g = __float_as_int(fv.z);
            if (cc >= 2) {
                int gold = (gpack[cc & 1] >> (4 * qi)) & 15;
                int oc   = q * 18 + gold;
                *(__half*)(Ab + a_off(base_t0, oc))     = __ushort_as_half((unsigned short)0);
                *(__half*)(Ab + a_off(base_t0, oc + 1)) = __ushort_as_half((unsigned short)0);
            }
            int col0 = q * 18 + g;
            *(__half*)(Ab + a_off(base_t0, col0))        = __float2half_rn(1.0f - fv.x);
            *(__half*)(Ab + a_off(base_t0, col0 + 1))    = __float2half_rn(fv.x);
            *(__half*)(Ab + a_off(base_t0, q * 18 + 17)) = __float2half_rn(fv.y);
            gpack[cc & 1] = (gpack[cc & 1] & ~(15u << (4 * qi))) | ((uint32_t)g << (4 * qi));
        }
    };

    build(0);

    const int ki0 = kh * 6;
    const int nki = 6 - kh;               // 6 or 5 k16 steps

    for (int cc = 0; cc < 16; cc++) {
        const int buf = cc & 1;
        // barrier: build(cc) visible; MMA(cc-1) LDS of same-parity buffer retired
        __syncthreads();

        // ---- MMA(cc): A via LDS (no redundancy), B via LDG quad-pipelined ----
        {
            const uint32_t abase = sbase + (buf ? SM_A1 : SM_A0)
                                 + (uint32_t)(wm * 2 * 5632 + lane * 16);
            const __half* Bc = g_Bfrag + (size_t)(c0 + cc) * (B_BYTES / 2) + lane * 4;
            uint2 bq[4], bn[4];
#pragma unroll
            for (int nt = 0; nt < 4; nt++)
                bq[nt] = __ldg((const uint2*)(Bc + (size_t)(ki0 * 8 + nt) * 128));
#pragma unroll
            for (int i = 0; i < 6; i++) {
                if (i >= nki) break;
                const int ki = ki0 + i;
                // issue quad1 loads for this ki
#pragma unroll
                for (int nt = 0; nt < 4; nt++)
                    bn[nt] = __ldg((const uint2*)(Bc + (size_t)(ki * 8 + 4 + nt) * 128));
                // A fragments for both mt
                uint32_t afr[2][4];
#pragma unroll
                for (int mt = 0; mt < 2; mt++) {
                    asm volatile("ld.shared.v4.b32 {%0,%1,%2,%3}, [%4];"
                                 : "=r"(afr[mt][0]), "=r"(afr[mt][1]),
                                   "=r"(afr[mt][2]), "=r"(afr[mt][3])
                                 : "r"(abase + (uint32_t)(mt * 5632 + ki * 512)));
                }
                // MMA quad0 (nt 0..3)
#pragma unroll
                for (int mt = 0; mt < 2; mt++)
#pragma unroll
                    for (int nt = 0; nt < 4; nt++)
                        mma16816(acc[mt][nt], afr[mt], (const uint32_t*)&bq[nt]);
                // preload next ki's quad0
                uint2 bq2[4];
                if (i + 1 < nki) {
#pragma unroll
                    for (int nt = 0; nt < 4; nt++)
                        bq2[nt] = __ldg((const uint2*)(Bc + (size_t)((ki + 1) * 8 + nt) * 128));
                }
                // MMA quad1 (nt 4..7)
#pragma unroll
                for (int mt = 0; mt < 2; mt++)
#pragma unroll
                    for (int nt = 0; nt < 4; nt++)
                        mma16816(acc[mt][4 + nt], afr[mt], (const uint32_t*)&bn[nt]);
                if (i + 1 < nki) {
#pragma unroll
                    for (int nt = 0; nt < 4; nt++) bq[nt] = bq2[nt];
                }
            }
        }

        // ---- build(cc+1) into the opposite A buffer (overlaps tensor-pipe drain) ----
        if (cc < 15) build(cc + 1);
    }

    // ---- epilogue: reduce K-halves via SMEM, then RED.ADD into out ----
    __syncthreads();                       // all MMA LDS done; A buffers reusable
    {
        float* red = (float*)smem;         // 32 KB region in A0/A1 space
        if (kh == 1) {
            float* dst = red + (size_t)(wm * 32 + lane) * 64;
#pragma unroll
            for (int mt = 0; mt < 2; mt++)
#pragma unroll
                for (int nt = 0; nt < 8; nt++)
                    *(float4*)(dst + (mt * 8 + nt) * 4) = *(const float4*)acc[mt][nt];
        }
        __syncthreads();
        if (kh == 0) {
            const float* src = red + (size_t)(wm * 32 + lane) * 64;
            const int gid = lane >> 2, tig = lane & 3;
#pragma unroll
            for (int mt = 0; mt < 2; mt++) {
#pragma unroll
                for (int nt = 0; nt < 8; nt++) {
                    float4 p = *(const float4*)(src + (mt * 8 + nt) * 4);
                    int f  = nt * 8 + 2 * tig;
                    int r0 = (wm * 2 + mt) * 16 + gid;
                    int r1 = r0 + 8;
                    float* o0 = out + (((size_t)(b * HO) + (h0 + (r0 >> 6))) * WO + (r0 & 63)) * NF + f;
                    float* o1 = out + (((size_t)(b * HO) + (h0 + (r1 >> 6))) * WO + (r1 & 63)) * NF + f;
                    atomicAdd(o0,     acc[mt][nt][0] + p.x);
                    atomicAdd(o0 + 1, acc[mt][nt][1] + p.y);
                    atomicAdd(o1,     acc[mt][nt][2] + p.z);
                    atomicAdd(o1 + 1, acc[mt][nt][3] + p.w);
                }
            }
        }
    }
}

// ---------------------------------------------------------------------------
extern "C" void kernel_launch(void* const* d_in, const int* in_sizes, int n_in,
                              void* d_out, int out_size)
{
    const float* x    = (const float*)d_in[0];   // (4,66,66,32)
    const float* cp   = (const float*)d_in[1];   // (64,32,3,3,17)
    const float* wsp  = (const float*)d_in[2];   // (64,32,3,3)
    const float* wsi  = (const float*)d_in[3];   // (64,32,3,3)
    const float* bias = (const float*)d_in[4];   // (64,)
    float* out        = (float*)d_out;           // (4,64,64,64)

    cudaFuncSetAttribute(kan_hmma_kernel, cudaFuncAttributeMaxDynamicSharedMemorySize, SM_TOTAL);

    prep_kernel<<<PREP_BLOCKS, 256>>>(x, cp, wsp, wsi, bias, out);
    kan_hmma_kernel<<<256, 256, SM_TOTAL>>>(out);
}

// round 16
// speedup vs baseline: 2.2257x; 1.0140x over previous
#include <cuda_runtime.h>
#include <cuda_fp16.h>
#include <cstdint>
#include <math.h>

// Problem constants
#define NB   4
#define NH   66
#define NW   66
#define NC   32
#define NF   64
#define HO   64
#define WO   64

// GEMM: per channel K = 176 (9 cij * 18 slots = 162 used, pad to 11 k16-steps)
#define KC        176
#define KI        11                  // k16 steps
#define A_BYTES   (128 * KC * 2)      // 45056 (fragment-major)
#define B_BYTES   (64 * KC * 2)       // 22528 (fragment-major)
#define NOUT      (NB * HO * WO * NF) // 1048576

// smem: two A fragment buffers (B via LDG from L2/L1); epilogue reduction reuses A0
#define SM_A0     0
#define SM_A1     45056
#define SM_TOTAL  90112

// fused prep kernel grid partition
#define PREP_BF_BLOCKS   352          // 90112 threads * 4 halves = 360448 B halves
#define PREP_FEAT_BLOCKS 2178         // 557568 feature elements
#define PREP_INIT_BLOCKS 1024         // 262144 float4 out-init
#define PREP_BLOCKS (PREP_BF_BLOCKS + PREP_FEAT_BLOCKS + PREP_INIT_BLOCKS)

// ---------------------------------------------------------------------------
// Device globals (no allocation allowed)
// B fragment images: [c][ki][ni][lane][4 halves]  (32 * 22528 B = 704 KB, L2-resident)
__device__ __align__(16) __half g_Bfrag[32 * (B_BYTES / 2)];
__device__ __align__(16) float4 g_featP[NC * NB * NH * NW];  // [c][b][h][w]: (t, silu, g-bits, 0)

// ---------------------------------------------------------------------------
__device__ __forceinline__ uint32_t smem_u32(const void* p) {
    uint32_t a;
    asm("{ .reg .u64 t; cvta.to.shared.u64 t, %1; cvt.u32.u64 %0, t; }" : "=r"(a) : "l"(p));
    return a;
}
__device__ __forceinline__ void mma16816(float* d, const uint32_t* a, const uint32_t* b) {
    asm volatile("mma.sync.aligned.m16n8k16.row.col.f32.f16.f16.f32 "
                 "{%0,%1,%2,%3}, {%4,%5,%6,%7}, {%8,%9}, {%0,%1,%2,%3};"
                 : "+f"(d[0]), "+f"(d[1]), "+f"(d[2]), "+f"(d[3])
                 : "r"(a[0]), "r"(a[1]), "r"(a[2]), "r"(a[3]), "r"(b[0]), "r"(b[1]));
}
// pair barrier: warps (wm, kh=0) and (wm, kh=1); ids 1..4
__device__ __forceinline__ void pair_bar(int wm) {
    asm volatile("bar.sync %0, 64;" :: "r"(wm + 1) : "memory");
}

// A fragment-major byte address for logical element (pixel r, col)
__device__ __forceinline__ uint32_t a_off(uint32_t base_t, int col) {
    int ki = col >> 4, kk = col & 15;
    return base_t + ki * 512 + (((kk >> 1) & 3) << 4) + ((kk & 1) << 1) + ((kk >> 3) << 3);
}

// ---------------------------------------------------------------------------
// Fused prep kernel: [0,352) B-fragments, [352,2530) features, [2530,3554) out=bias
__global__ void prep_kernel(const float* __restrict__ x,
                            const float* __restrict__ cp,
                            const float* __restrict__ w_spline,
                            const float* __restrict__ w_silu,
                            const float* __restrict__ bias,
                            float* __restrict__ out)
{
    int bid = blockIdx.x;
    int tid = threadIdx.x;

    if (bid < PREP_BF_BLOCKS) {
        int t    = bid * 256 + tid;                 // [0, 90112)
        int lane = t & 31;
        int ni   = (t >> 5) & 7;
        int rest = t >> 8;
        int ki   = rest % KI;
        int c    = rest / KI;
        int gid  = lane >> 2, tig = lane & 3;
        int f    = ni * 8 + gid;
        int kbase = ki * 16 + 2 * tig;
        __half h[4];
#pragma unroll
        for (int bb = 0; bb < 4; bb++) {
            int k = kbase + (bb & 1) + ((bb >> 1) << 3);
            float v = 0.0f;
            if (k < 162) {
                int q = k / 18;
                int s = k - 18 * q;
                int iw = (f * 32 + c) * 9 + q;
                v = (s < 17) ? w_spline[iw] * cp[iw * 17 + s] : w_silu[iw];
            }
            h[bb] = __float2half_rn(v);
        }
        *(uint2*)(g_Bfrag + (size_t)t * 4) = *(const uint2*)h;
    } else if (bid < PREP_BF_BLOCKS + PREP_FEAT_BLOCKS) {
        int i = (bid - PREP_BF_BLOCKS) * 256 + tid;  // [0, 557568)
        int c   = i & 31;
        int pos = i >> 5;
        float v  = x[i];
        float s  = v / (1.0f + __expf(-v));
        float xc = fminf(1.0f, fmaxf(-1.0f, v));
        float u  = (xc + 1.0f) * 8.0f;
        int   g  = (int)u;
        g = (g > 15) ? 15 : g;
        float t  = u - (float)g;
        g_featP[(size_t)c * (NB * NH * NW) + pos] = make_float4(t, s, __int_as_float(g), 0.0f);
    } else {
        int j = (bid - PREP_BF_BLOCKS - PREP_FEAT_BLOCKS) * 256 + tid;  // [0, 262144)
        ((float4*)out)[j] = __ldg(((const float4*)bias) + (j & 15));
    }
}

// ---------------------------------------------------------------------------
// Main HMMA kernel: 256 blocks x 256 threads, 2 blocks/SM (90KB smem, <=128 regs).
// Block = (split s, b, 2 output rows) = 128 px, 16 channels [s*16, +16).
// Warp (wm = wid&3, kh = wid>>2): M rows [32*wm, +32), ALL 64 f, K-half kh.
// All A data for rows [32wm,+32) is produced and consumed ONLY by the warp pair
// (wm,0)+(wm,1) -> per-pair named barriers replace block-wide __syncthreads:
// 4 independent channel pipelines per block, no cross-pair straggler coupling.
__global__ void __launch_bounds__(256, 2)
kan_hmma_kernel(float* __restrict__ out)
{
    extern __shared__ char smem[];
    const uint32_t sbase = smem_u32(smem);
    const int tid  = threadIdx.x;
    const int wid  = tid >> 5;
    const int lane = tid & 31;
    const int blk  = blockIdx.x;
    const int s    = blk >> 7;            // channel split (0,1)
    const int b    = (blk >> 5) & 3;
    const int h0   = (blk & 31) * 2;
    const int c0   = s * 16;

    // zero both A fragment buffers (cols never written stay 0 forever)
    {
        float4* az = (float4*)smem;
#pragma unroll 4
        for (int i = tid; i < (2 * A_BYTES) / 16; i += 256) az[i] = make_float4(0.f, 0.f, 0.f, 0.f);
    }
    __syncthreads();   // A zeroing visible before scatter (block-wide, once)

    // scatter config: threads 0-127 -> pixel r, q 0..3; 128-255 -> same r, q 4..8
    const int r     = tid & 127;
    const int qbase = (tid >> 7) ? 4 : 0;
    const int qcnt  = (tid >> 7) ? 5 : 4;
    const int rh    = r >> 6, rw = r & 63;
    const int mi    = r >> 4, row16 = r & 15;
    const uint32_t base_t0 = (uint32_t)(mi * 5632 + ((row16 & 7) << 6) + (((row16 >> 3) & 1) << 2));

    const int wm = wid & 3;               // M group (32 px) == pair id
    const int kh = wid >> 2;              // K half: 0 -> ki 0..5, 1 -> ki 6..10

    float acc[2][8][4];
#pragma unroll
    for (int mt = 0; mt < 2; mt++)
#pragma unroll
        for (int nt = 0; nt < 8; nt++)
#pragma unroll
            for (int e = 0; e < 4; e++) acc[mt][nt][e] = 0.0f;

    uint32_t gpack[2] = {0u, 0u};

    // build A(cc) into buffer cc&1 (zero stale slots from cc-2 first)
    auto build = [&](int cc) {
        char* Ab = smem + ((cc & 1) ? SM_A1 : SM_A0);
        int ca = c0 + cc;
#pragma unroll
        for (int qi = 0; qi < 5; qi++) {
            if (qi >= qcnt) break;
            int q  = qbase + qi;
            int ii = q / 3, jj = q - 3 * ii;
            float4 fv = __ldg(g_featP + ((size_t)(ca * NB + b) * NH + (h0 + rh + ii)) * NW + (rw + jj));
            int g = __float_as_int(fv.z);
            if (cc >= 2) {
                int gold = (gpack[cc & 1] >> (4 * qi)) & 15;
                int oc   = q * 18 + gold;
                *(__half*)(Ab + a_off(base_t0, oc))     = __ushort_as_half((unsigned short)0);
                *(__half*)(Ab + a_off(base_t0, oc + 1)) = __ushort_as_half((unsigned short)0);
            }
            int col0 = q * 18 + g;
            *(__half*)(Ab + a_off(base_t0, col0))        = __float2half_rn(1.0f - fv.x);
            *(__half*)(Ab + a_off(base_t0, col0 + 1))    = __float2half_rn(fv.x);
            *(__half*)(Ab + a_off(base_t0, q * 18 + 17)) = __float2half_rn(fv.y);
            gpack[cc & 1] = (gpack[cc & 1] & ~(15u << (4 * qi))) | ((uint32_t)g << (4 * qi));
        }
    };

    build(0);

    const int ki0 = kh * 6;
    const int nki = 6 - kh;               // 6 or 5 k16 steps

    for (int cc = 0; cc < 16; cc++) {
        const int buf = cc & 1;
        // pair barrier: partner's build(cc) visible; partner's MMA(cc-1) retired
        pair_bar(wm);

        // ---- MMA(cc): A via LDS (read-once), B via LDG quad-pipelined ----
        {
            const uint32_t abase = sbase + (buf ? SM_A1 : SM_A0)
                                 + (uint32_t)(wm * 2 * 5632 + lane * 16);
            const __half* Bc = g_Bfrag + (size_t)(c0 + cc) * (B_BYTES / 2) + lane * 4;
            uint2 bq[4], bn[4];
#pragma unroll
            for (int nt = 0; nt < 4; nt++)
                bq[nt] = __ldg((const uint2*)(Bc + (size_t)(ki0 * 8 + nt) * 128));
#pragma unroll
            for (int i = 0; i < 6; i++) {
                if (i >= nki) break;
                const int ki = ki0 + i;
                // issue quad1 loads for this ki
#pragma unroll
                for (int nt = 0; nt < 4; nt++)
                    bn[nt] = __ldg((const uint2*)(Bc + (size_t)(ki * 8 + 4 + nt) * 128));
                // A fragments for both mt
                uint32_t afr[2][4];
#pragma unroll
                for (int mt = 0; mt < 2; mt++) {
                    asm volatile("ld.shared.v4.b32 {%0,%1,%2,%3}, [%4];"
                                 : "=r"(afr[mt][0]), "=r"(afr[mt][1]),
                                   "=r"(afr[mt][2]), "=r"(afr[mt][3])
                                 : "r"(abase + (uint32_t)(mt * 5632 + ki * 512)));
                }
                // MMA quad0 (nt 0..3)
#pragma unroll
                for (int mt = 0; mt < 2; mt++)
#pragma unroll
                    for (int nt = 0; nt < 4; nt++)
                        mma16816(acc[mt][nt], afr[mt], (const uint32_t*)&bq[nt]);
                // preload next ki's quad0
                uint2 bq2[4];
                if (i + 1 < nki) {
#pragma unroll
                    for (int nt = 0; nt < 4; nt++)
                        bq2[nt] = __ldg((const uint2*)(Bc + (size_t)((ki + 1) * 8 + nt) * 128));
                }
                // MMA quad1 (nt 4..7)
#pragma unroll
                for (int mt = 0; mt < 2; mt++)
#pragma unroll
                    for (int nt = 0; nt < 4; nt++)
                        mma16816(acc[mt][4 + nt], afr[mt], (const uint32_t*)&bn[nt]);
                if (i + 1 < nki) {
#pragma unroll
                    for (int nt = 0; nt < 4; nt++) bq[nt] = bq2[nt];
                }
            }
        }

        // ---- build(cc+1) into the opposite A buffer (overlaps tensor-pipe drain) ----
        if (cc < 15) build(cc + 1);
    }

    // ---- epilogue (pair-local): reduce K-halves via pair's own A0 region ----
    {
        // pair barrier: both warps' MMA(15) (reads of A1 rows) and MMA(14) (A0) retired
        pair_bar(wm);
        float* red = (float*)(smem + wm * 11264);    // 8KB inside pair's A0 row region
        if (kh == 1) {
            float* dst = red + (size_t)lane * 64;
#pragma unroll
            for (int mt = 0; mt < 2; mt++)
#pragma unroll
                for (int nt = 0; nt < 8; nt++)
                    *(float4*)(dst + (mt * 8 + nt) * 4) = *(const float4*)acc[mt][nt];
        }
        pair_bar(wm);
        if (kh == 0) {
            const float* src = red + (size_t)lane * 64;
            const int gid = lane >> 2, tig = lane & 3;
#pragma unroll
            for (int mt = 0; mt < 2; mt++) {
#pragma unroll
                for (int nt = 0; nt < 8; nt++) {
                    float4 p = *(const float4*)(src + (mt * 8 + nt) * 4);
                    int f  = nt * 8 + 2 * tig;
                    int r0 = (wm * 2 + mt) * 16 + gid;
                    int r1 = r0 + 8;
                    float* o0 = out + (((size_t)(b * HO) + (h0 + (r0 >> 6))) * WO + (r0 & 63)) * NF + f;
                    float* o1 = out + (((size_t)(b * HO) + (h0 + (r1 >> 6))) * WO + (r1 & 63)) * NF + f;
                    atomicAdd(o0,     acc[mt][nt][0] + p.x);
                    atomicAdd(o0 + 1, acc[mt][nt][1] + p.y);
                    atomicAdd(o1,     acc[mt][nt][2] + p.z);
                    atomicAdd(o1 + 1, acc[mt][nt][3] + p.w);
                }
            }
        }
    }
}

// ---------------------------------------------------------------------------
extern "C" void kernel_launch(void* const* d_in, const int* in_sizes, int n_in,
                              void* d_out, int out_size)
{
    const float* x    = (const float*)d_in[0];   // (4,66,66,32)
    const float* cp   = (const float*)d_in[1];   // (64,32,3,3,17)
    const float* wsp  = (const float*)d_in[2];   // (64,32,3,3)
    const float* wsi  = (const float*)d_in[3];   // (64,32,3,3)
    const float* bias = (const float*)d_in[4];   // (64,)
    float* out        = (float*)d_out;           // (4,64,64,64)

    cudaFuncSetAttribute(kan_hmma_kernel, cudaFuncAttributeMaxDynamicSharedMemorySize, SM_TOTAL);

    prep_kernel<<<PREP_BLOCKS, 256>>>(x, cp, wsp, wsi, bias, out);
    kan_hmma_kernel<<<256, 256, SM_TOTAL>>>(out);
}